// round 6
// baseline (speedup 1.0000x reference)
#include <cuda_runtime.h>
#include <cstdint>

#define BATCH   4
#define NF      16
#define NC      8
#define NPIX    262144            // 512*512
#define DELTA_V 0.5f
#define CMAX    100000.0f

// K1 config (proven): 64 chunks per batch, 256 threads (4 fg x 2 pw warps)
#define CHUNKS    64
#define K1_THREADS 256
#define PAIRS_PER_CHUNK 2048      // (NPIX/2)/CHUNKS
#define K1_ITERS  32              // PAIRS_PER_CHUNK / 64 pixel-threads

// K3 config: 128 blocks per batch x 256 threads; 2048 px/block; 8 px/thread
#define K3_BLOCKS  128
#define K3_THREADS 256
#define PIX_PER_K3BLK 2048
#define TOTAL_K3   (BATCH * K3_BLOCKS)   // 512

typedef unsigned long long u64;

// ---- scratch (device globals; fully rewritten every launch) ----
__device__ float g_part1 [BATCH][CHUNKS][NF][NC];
__device__ float g_part1c[BATCH][CHUNKS][NC];
__device__ float g_part2 [TOTAL_K3];
__device__ unsigned g_fin_count = 0;

// ---- packed f32x2 helpers (Blackwell) ----
__device__ __forceinline__ u64 pack2(float lo, float hi) {
    u64 r; asm("mov.b64 %0, {%1, %2};" : "=l"(r) : "f"(lo), "f"(hi)); return r;
}
__device__ __forceinline__ void unpack2(u64 v, float& lo, float& hi) {
    asm("mov.b64 {%0, %1}, %2;" : "=f"(lo), "=f"(hi) : "l"(v));
}
__device__ __forceinline__ u64 fma2(u64 a, u64 b, u64 c) {
    u64 d; asm("fma.rn.f32x2 %0, %1, %2, %3;" : "=l"(d) : "l"(a), "l"(b), "l"(c)); return d;
}
__device__ __forceinline__ u64 add2(u64 a, u64 b) {
    u64 d; asm("add.rn.f32x2 %0, %1, %2;" : "=l"(d) : "l"(a), "l"(b)); return d;
}

// ============================================================================
// K1: masked per-class sums + counts (packed f32x2). Unchanged (near floor).
// ============================================================================
__global__ void __launch_bounds__(K1_THREADS)
k1_sums(const float* __restrict__ pred, const int* __restrict__ tgt)
{
    const int tid  = threadIdx.x;
    const int w    = tid >> 5;
    const int lane = tid & 31;
    const int fg   = w & 3;
    const int pw   = w >> 2;
    const int pl   = pw * 32 + lane;          // pixel-thread 0..63
    const int b    = blockIdx.y;

    const float* p0 = pred + (size_t)(b * NF + fg * 4) * NPIX;
    const int*   t0 = tgt  + (size_t)b * NPIX;
    const int basePair = blockIdx.x * PAIRS_PER_CHUNK;

    u64 acc[4][NC];
    u64 cnt[NC];
#pragma unroll
    for (int f = 0; f < 4; f++)
#pragma unroll
        for (int c = 0; c < NC; c++) acc[f][c] = 0ULL;
#pragma unroll
    for (int c = 0; c < NC; c++) cnt[c] = 0ULL;

    for (int i = 0; i < K1_ITERS; i++) {
        const int pair = basePair + i * 64 + pl;
        const int n0   = pair * 2;
        const int2 g   = *(const int2*)(t0 + n0);

        u64 m[NC];
#pragma unroll
        for (int c = 0; c < NC; c++)
            m[c] = pack2(g.x == c ? 1.0f : 0.0f, g.y == c ? 1.0f : 0.0f);

#pragma unroll
        for (int f = 0; f < 4; f++) {
            const u64 v = *(const u64*)(p0 + (size_t)f * NPIX + n0);
#pragma unroll
            for (int c = 0; c < NC; c++)
                acc[f][c] = fma2(v, m[c], acc[f][c]);
        }
        if (fg == 0) {
#pragma unroll
            for (int c = 0; c < NC; c++) cnt[c] = add2(cnt[c], m[c]);
        }
    }

#pragma unroll
    for (int f = 0; f < 4; f++)
#pragma unroll
        for (int c = 0; c < NC; c++)
            for (int o = 16; o > 0; o >>= 1)
                acc[f][c] = add2(acc[f][c], __shfl_xor_sync(0xffffffffu, acc[f][c], o));
    if (fg == 0) {
#pragma unroll
        for (int c = 0; c < NC; c++)
            for (int o = 16; o > 0; o >>= 1)
                cnt[c] = add2(cnt[c], __shfl_xor_sync(0xffffffffu, cnt[c], o));
    }

    __shared__ float s_s[4][2][4][NC];
    __shared__ float s_c[2][NC];
    if (lane == 0) {
#pragma unroll
        for (int f = 0; f < 4; f++)
#pragma unroll
            for (int c = 0; c < NC; c++) {
                float lo, hi; unpack2(acc[f][c], lo, hi);
                s_s[fg][pw][f][c] = lo + hi;
            }
        if (fg == 0) {
#pragma unroll
            for (int c = 0; c < NC; c++) {
                float lo, hi; unpack2(cnt[c], lo, hi);
                s_c[pw][c] = lo + hi;
            }
        }
    }
    __syncthreads();

    if (tid < 128) {
        const int fg2 = tid >> 5, f2 = (tid >> 3) & 3, c2 = tid & 7;
        __stcg(&g_part1[b][blockIdx.x][fg2 * 4 + f2][c2],
               s_s[fg2][0][f2][c2] + s_s[fg2][1][f2][c2]);
    }
    if (tid < NC)
        __stcg(&g_part1c[b][blockIdx.x][tid], s_c[0][tid] + s_c[1][tid]);
}

// ============================================================================
// K3: means (redundant per block) -> variance loss (2 interleaved quad
//     streams per thread) -> last-block final reduce
// ============================================================================
__global__ void __launch_bounds__(K3_THREADS)
k3_dist(const float* __restrict__ pred, const int* __restrict__ tgt,
        float* __restrict__ out)
{
    const int tid  = threadIdx.x;
    const int w    = tid >> 5;
    const int lane = tid & 31;
    const int b    = blockIdx.y;
    const int blk  = blockIdx.x;

    __shared__ float  s_tmp[128][2];
    __shared__ float  s_ctmp[NC][2];
    __shared__ float  s_cnt[NC];
    __shared__ float4 s_m4[4][NC];       // [feature-group][class] -> 4 features
    __shared__ float  s_factor;
    __shared__ float  s_red[8];
    __shared__ float  s_f2[8];
    __shared__ unsigned s_last;

    // ---- counts: 16 threads, 2-way split ----
    if (tid < 16) {
        const int c = tid >> 1, part = tid & 1;
        float s = 0.f;
#pragma unroll
        for (int i = 0; i < CHUNKS / 2; i++)
            s += __ldcg(&g_part1c[b][part * (CHUNKS / 2) + i][c]);
        s_ctmp[c][part] = s;
    }
    // ---- feature-class sums: 256 threads, 2-way split ----
    {
        const int idx = tid >> 1, part = tid & 1;   // idx = f*8+c
        const int f = idx >> 3, c = idx & 7;
        float s = 0.f;
#pragma unroll
        for (int i = 0; i < CHUNKS / 2; i++)
            s += __ldcg(&g_part1[b][part * (CHUNKS / 2) + i][f][c]);
        s_tmp[idx][part] = s;
    }
    __syncthreads();
    if (tid < NC)
        s_cnt[tid] = s_ctmp[tid][0] + s_ctmp[tid][1];
    __syncthreads();
    if (tid < 128) {
        const int f = tid >> 3, c = tid & 7;
        ((float*)&s_m4[f >> 2][c])[f & 3] = (s_tmp[tid][0] + s_tmp[tid][1]) / s_cnt[c];
    }
    if (tid == K3_THREADS - 1) {
        float fs = 0.f;
#pragma unroll
        for (int c = 0; c < NC; c++) fs += 1.0f / s_cnt[c];
        s_factor = fs * (1.0f / NC);
    }
    __syncthreads();

    // ---- pass 2: two interleaved quad streams per thread ----
    const float* pb = pred + (size_t)b * NF * NPIX;
    const int*   t0 = tgt  + (size_t)b * NPIX;
    const int nA = blk * PIX_PER_K3BLK + tid * 4;          // quad A
    const int nB = nA + K3_THREADS * 4;                    // quad B (+1024 px)

    const int4 gA = __ldg((const int4*)(t0 + nA));
    const int4 gB = __ldg((const int4*)(t0 + nB));

    float sqA0 = 0.f, sqA1 = 0.f, sqA2 = 0.f, sqA3 = 0.f;
    float sqB0 = 0.f, sqB1 = 0.f, sqB2 = 0.f, sqB3 = 0.f;

#pragma unroll
    for (int fg = 0; fg < 4; fg++) {
        const float4 mAx = s_m4[fg][gA.x];
        const float4 mAy = s_m4[fg][gA.y];
        const float4 mAz = s_m4[fg][gA.z];
        const float4 mAw = s_m4[fg][gA.w];
        const float4 mBx = s_m4[fg][gB.x];
        const float4 mBy = s_m4[fg][gB.y];
        const float4 mBz = s_m4[fg][gB.z];
        const float4 mBw = s_m4[fg][gB.w];
        const float* pfA = pb + (size_t)(fg * 4) * NPIX + nA;
        const float* pfB = pb + (size_t)(fg * 4) * NPIX + nB;
#pragma unroll
        for (int j = 0; j < 4; j++) {
            const float4 vA = __ldcs((const float4*)(pfA + (size_t)j * NPIX));
            const float4 vB = __ldcs((const float4*)(pfB + (size_t)j * NPIX));
            float d;
            d = ((const float*)&mAx)[j] - vA.x; sqA0 = fmaf(d, d, sqA0);
            d = ((const float*)&mBx)[j] - vB.x; sqB0 = fmaf(d, d, sqB0);
            d = ((const float*)&mAy)[j] - vA.y; sqA1 = fmaf(d, d, sqA1);
            d = ((const float*)&mBy)[j] - vB.y; sqB1 = fmaf(d, d, sqB1);
            d = ((const float*)&mAz)[j] - vA.z; sqA2 = fmaf(d, d, sqA2);
            d = ((const float*)&mBz)[j] - vB.z; sqB2 = fmaf(d, d, sqB2);
            d = ((const float*)&mAw)[j] - vA.w; sqA3 = fmaf(d, d, sqA3);
            d = ((const float*)&mBw)[j] - vB.w; sqB3 = fmaf(d, d, sqB3);
        }
    }

    float local = 0.f;
    {
        float dd, tt;
        dd = sqrtf(sqA0); tt = fminf(fmaxf(dd - DELTA_V, 0.f), CMAX); local = fmaf(tt, tt, local);
        dd = sqrtf(sqA1); tt = fminf(fmaxf(dd - DELTA_V, 0.f), CMAX); local = fmaf(tt, tt, local);
        dd = sqrtf(sqA2); tt = fminf(fmaxf(dd - DELTA_V, 0.f), CMAX); local = fmaf(tt, tt, local);
        dd = sqrtf(sqA3); tt = fminf(fmaxf(dd - DELTA_V, 0.f), CMAX); local = fmaf(tt, tt, local);
        dd = sqrtf(sqB0); tt = fminf(fmaxf(dd - DELTA_V, 0.f), CMAX); local = fmaf(tt, tt, local);
        dd = sqrtf(sqB1); tt = fminf(fmaxf(dd - DELTA_V, 0.f), CMAX); local = fmaf(tt, tt, local);
        dd = sqrtf(sqB2); tt = fminf(fmaxf(dd - DELTA_V, 0.f), CMAX); local = fmaf(tt, tt, local);
        dd = sqrtf(sqB3); tt = fminf(fmaxf(dd - DELTA_V, 0.f), CMAX); local = fmaf(tt, tt, local);
    }

    // block reduce (fixed order)
    for (int o = 16; o > 0; o >>= 1)
        local += __shfl_xor_sync(0xffffffffu, local, o);
    if (lane == 0) s_red[w] = local;
    __syncthreads();
    if (tid < 32) {
        float v = (tid < 8) ? s_red[tid] : 0.f;
        for (int o = 16; o > 0; o >>= 1)
            v += __shfl_xor_sync(0xffffffffu, v, o);
        if (tid == 0) __stcg(&g_part2[b * K3_BLOCKS + blk], v * s_factor);
    }

    // ---- last-block final reduction of 512 partials ----
    __syncthreads();
    if (tid == 0) {
        __threadfence();
        s_last = (atomicAdd(&g_fin_count, 1) == TOTAL_K3 - 1) ? 1u : 0u;
    }
    __syncthreads();
    if (s_last) {
        float v = __ldcg(&g_part2[tid]) + __ldcg(&g_part2[tid + 256]);
        for (int o = 16; o > 0; o >>= 1)
            v += __shfl_xor_sync(0xffffffffu, v, o);
        if (lane == 0) s_f2[w] = v;
        __syncthreads();
        if (tid == 0) {
            out[0] = ((s_f2[0] + s_f2[1]) + (s_f2[2] + s_f2[3]))
                   + ((s_f2[4] + s_f2[5]) + (s_f2[6] + s_f2[7]));
            g_fin_count = 0;   // reset for next graph replay
        }
    }
}

// ============================================================================
extern "C" void kernel_launch(void* const* d_in, const int* in_sizes, int n_in,
                              void* d_out, int out_size)
{
    const float* pred = (const float*)d_in[0];
    const int*   tgt  = (const int*)d_in[1];
    float* out = (float*)d_out;

    k1_sums<<<dim3(CHUNKS, BATCH), K1_THREADS>>>(pred, tgt);
    k3_dist<<<dim3(K3_BLOCKS, BATCH), K3_THREADS>>>(pred, tgt, out);
}